// round 11
// baseline (speedup 1.0000x reference)
#include <cuda_runtime.h>
#include <cstdint>

// ---------------------------------------------------------------------------
// voltageNN: 2-layer LSTM (H=256, proj P=1, in=1, T=1000) + MLP head, B=16384.
// R8 structure (1 elem/warp, pipe-balanced activation split) with the register
// budget cut to reach 5 blocks/SM (5 warps/SMSP) for dual-pipe overlap:
//   MUFU: i,f,g gates (24) + tanh(c) pairs 0,1 (4)      -> tanh.approx.f32
//   FMA : o gate (8) + tanh(c) pairs 2,3 (4)            -> deg-13 Chebyshev,
//                                                          packed fma.rn.f32x2
// Whh AND bias live in SMEM as split lo/hi f32 planes (conflict-free LDS.32,
// volatile so they never enter the register budget). wx/wr/poly stay in regs.
// ---------------------------------------------------------------------------

#define HID   256
#define TLEN  1000
#define FULLM 0xffffffffu
#define FIT_L    1.8
#define FALLBACK 1.75f
#define NPOLY 7            // deg-13 odd: coeffs of u^1..u^13

typedef unsigned long long u64;

// Packed f32-pair weights: [layer][pair 0..3][gate i,f,o,g][lane].
// lo = unit (lane + 64*pair), hi = unit (+32). i/f/o pre-scaled by 0.5
// (sigmoid(x) = 0.5*tanh(0.5x)+0.5).
__device__ float2 g_wx2[2][4][4][32];
__device__ float2 g_wh2[2][4][4][32];
__device__ float2 g_wb2[2][4][4][32];
__device__ float2 g_wr2[2][4][32];       // projection Whr pairs
__device__ float  g_poly[NPOLY];         // tanh odd-poly coeffs (deg 13)
__device__ float  g_w1t[TLEN * 128];     // W1 transposed + padded: [t][j]
__device__ float  g_b1p[128];
__device__ float  g_w2p[128];

// ---- f32x2 packed helpers (sm_100+) ----
__device__ __forceinline__ u64 pack2(float lo, float hi) {
    u64 r; asm("mov.b64 %0, {%1, %2};" : "=l"(r) : "f"(lo), "f"(hi)); return r;
}
__device__ __forceinline__ void unpack2(u64 v, float& lo, float& hi) {
    asm("mov.b64 {%0, %1}, %2;" : "=f"(lo), "=f"(hi) : "l"(v));
}
__device__ __forceinline__ u64 fma2(u64 a, u64 b, u64 c) {
    u64 r; asm("fma.rn.f32x2 %0, %1, %2, %3;" : "=l"(r) : "l"(a), "l"(b), "l"(c));
    return r;
}
__device__ __forceinline__ u64 mul2(u64 a, u64 b) {
    u64 r; asm("mul.rn.f32x2 %0, %1, %2;" : "=l"(r) : "l"(a), "l"(b)); return r;
}
__device__ __forceinline__ u64 ldp(const float2* p) {
    float2 v = *p; return pack2(v.x, v.y);
}
__device__ __forceinline__ float tanh_fast(float x) {
    float y; asm("tanh.approx.f32 %0, %1;" : "=f"(y) : "f"(x)); return y;
}
__device__ __forceinline__ uint32_t smem_u32(const void* p) {
    uint32_t a;
    asm("{ .reg .u64 t; cvta.to.shared.u64 t, %1; cvt.u32.u64 %0, t; }"
        : "=r"(a) : "l"(p));
    return a;
}
// volatile LDS.32: keeps loop-invariant weights out of the register budget;
// 4-byte lane stride in the plane layout -> conflict-free.
__device__ __forceinline__ float lds32v(uint32_t addr) {
    float r; asm volatile("ld.shared.f32 %0, [%1];" : "=f"(r) : "r"(addr));
    return r;
}
// deg-13 odd polynomial tanh on packed pair (valid on |u| <= FIT_L).
__device__ __forceinline__ u64 tanh_poly2(u64 u2, const u64* B) {
    u64 s2 = mul2(u2, u2);
    u64 p = B[6];
    p = fma2(p, s2, B[5]);
    p = fma2(p, s2, B[4]);
    p = fma2(p, s2, B[3]);
    p = fma2(p, s2, B[2]);
    p = fma2(p, s2, B[1]);
    p = fma2(p, s2, B[0]);
    return mul2(p, u2);
}

// ---------------------------------------------------------------------------
// Prep kernel: pack/transpose weights + runtime Chebyshev fit of tanh.
// grid = TLEN+1 blocks x 128 threads.
// ---------------------------------------------------------------------------
__global__ void prep_kernel(
    const float* __restrict__ Wih0, const float* __restrict__ Whh0,
    const float* __restrict__ bih0, const float* __restrict__ bhh0,
    const float* __restrict__ Whr0,
    const float* __restrict__ Wih1, const float* __restrict__ Whh1,
    const float* __restrict__ bih1, const float* __restrict__ bhh1,
    const float* __restrict__ Whr1,
    const float* __restrict__ W1,  const float* __restrict__ b1,
    const float* __restrict__ W2)
{
    int tid = threadIdx.x;
    int blk = blockIdx.x;
    if (blk < TLEN) {
        int t = blk;
        int j = tid;  // 0..127
        g_w1t[t * 128 + j] = (j < 100) ? W1[j * TLEN + t] : 0.0f;
        return;
    }
    // ---- pack LSTM weights: 2 layers x 4 pairs x 32 lanes ----
    for (int i = tid; i < 256; i += 128) {
        int layer = i >> 7;
        int rem   = i & 127;
        int p     = rem >> 5;
        int lane  = rem & 31;
        int klo = lane + 64 * p;
        int khi = klo + 32;
        const float* Wih = layer ? Wih1 : Wih0;
        const float* Whh = layer ? Whh1 : Whh0;
        const float* bih = layer ? bih1 : bih0;
        const float* bhh = layer ? bhh1 : bhh0;
        const float* Whr = layer ? Whr1 : Whr0;
        // source gate stacking: i [0,256), f [256,512), g [512,768), o [768,1024)
        const int rows[4] = {0, 256, 768, 512};   // our order: i, f, o, g
        const float scl[4] = {0.5f, 0.5f, 0.5f, 1.0f};
#pragma unroll
        for (int gte = 0; gte < 4; gte++) {
            int r = rows[gte];
            float s = scl[gte];
            g_wx2[layer][p][gte][lane] = make_float2(s * Wih[r + klo], s * Wih[r + khi]);
            g_wh2[layer][p][gte][lane] = make_float2(s * Whh[r + klo], s * Whh[r + khi]);
            g_wb2[layer][p][gte][lane] = make_float2(s * (bih[r + klo] + bhh[r + klo]),
                                                     s * (bih[r + khi] + bhh[r + khi]));
        }
        g_wr2[layer][p][lane] = make_float2(Whr[klo], Whr[khi]);
    }
    if (tid < 128) {
        g_b1p[tid] = (tid < 100) ? b1[tid] : 0.0f;
        g_w2p[tid] = (tid < 100) ? W2[tid] : 0.0f;
    }
    // ---- Chebyshev fit of tanh on [-L, L], deg 13 odd, runtime in double ----
    if (tid == 0) {
        const double PI = 3.14159265358979323846;
        const double L = FIT_L;
        const int KMAX = 13, NN = 64;
        double c[KMAX + 1];
        for (int k = 0; k <= KMAX; k++) {
            double s = 0.0;
            for (int j = 0; j < NN; j++) {
                double th = PI * (j + 0.5) / NN;
                s += tanh(L * cos(th)) * cos(k * th);
            }
            c[k] = 2.0 / NN * s;
        }
        double T[KMAX + 1][KMAX + 1];
        for (int k = 0; k <= KMAX; k++)
            for (int i = 0; i <= KMAX; i++) T[k][i] = 0.0;
        T[0][0] = 1.0; T[1][1] = 1.0;
        for (int k = 2; k <= KMAX; k++)
            for (int i = 0; i <= KMAX; i++)
                T[k][i] = 2.0 * (i > 0 ? T[k - 1][i - 1] : 0.0) - T[k - 2][i];
        double mono[KMAX + 1];
        for (int i = 0; i <= KMAX; i++) mono[i] = 0.0;
        for (int k = 1; k <= KMAX; k += 2)          // odd terms only
            for (int i = 0; i <= KMAX; i++) mono[i] += c[k] * T[k][i];
        double Lp = L;
        for (int m = 0; m < NPOLY; m++) {           // coeff of u^(2m+1)
            g_poly[m] = (float)(mono[2 * m + 1] / Lp);
            Lp *= L * L;
        }
    }
}

// ---------------------------------------------------------------------------
// One LSTM step: 8 units/lane as 4 (lo,hi) pairs.
//   MUFU: i,f,g all pairs; tanh(c) pairs 0,1.  Poly: o all pairs; tanh(c) 2,3.
// Whh and bias come from SMEM planes (wh/wb addr = per-lane base; per-gate
// stride 256B, hi plane at +128B). Exact-MUFU fallback for |arg| > FALLBACK.
// ---------------------------------------------------------------------------
__device__ __forceinline__ float lstm_step(
    float xv, float h,
    const u64 (*wx)[4], const u64* wr, float* c, const u64* B,
    uint32_t whaddr, uint32_t wbaddr)
{
    const u64 halfc = pack2(0.5f, 0.5f);
    u64 x2 = pack2(xv, xv);
    u64 h2 = pack2(h, h);
    u64 part2 = 0ull;
    float runmax = 0.0f;
#pragma unroll
    for (int p = 0; p < 4; p++) {
        // weights/bias from shared planes (volatile; not in regs)
        uint32_t off = (uint32_t)(p * 4) * 256u;
        u64 whi = pack2(lds32v(whaddr + off        ), lds32v(whaddr + off + 128));
        u64 whf = pack2(lds32v(whaddr + off + 256  ), lds32v(whaddr + off + 384));
        u64 who = pack2(lds32v(whaddr + off + 512  ), lds32v(whaddr + off + 640));
        u64 whg = pack2(lds32v(whaddr + off + 768  ), lds32v(whaddr + off + 896));
        u64 wbi = pack2(lds32v(wbaddr + off        ), lds32v(wbaddr + off + 128));
        u64 wbf = pack2(lds32v(wbaddr + off + 256  ), lds32v(wbaddr + off + 384));
        u64 wbo = pack2(lds32v(wbaddr + off + 512  ), lds32v(wbaddr + off + 640));
        u64 wbg = pack2(lds32v(wbaddr + off + 768  ), lds32v(wbaddr + off + 896));
        u64 ai2 = fma2(x2, wx[p][0], fma2(h2, whi, wbi));
        u64 af2 = fma2(x2, wx[p][1], fma2(h2, whf, wbf));
        u64 ao2 = fma2(x2, wx[p][2], fma2(h2, who, wbo));
        u64 ag2 = fma2(x2, wx[p][3], fma2(h2, whg, wbg));
        float ail, aih, afl, afh, agl, agh, aol, aoh;
        unpack2(ai2, ail, aih);
        unpack2(af2, afl, afh);
        unpack2(ag2, agl, agh);
        unpack2(ao2, aol, aoh);
        // MUFU: i, f (sigmoid via 0.5-prescaled tanh), g (tanh)
        float gil = fmaf(tanh_fast(ail), 0.5f, 0.5f);
        float gih = fmaf(tanh_fast(aih), 0.5f, 0.5f);
        float gfl = fmaf(tanh_fast(afl), 0.5f, 0.5f);
        float gfh = fmaf(tanh_fast(afh), 0.5f, 0.5f);
        float ggl = tanh_fast(agl);
        float ggh = tanh_fast(agh);
        // cell update (scalar)
        float cl = fmaf(gfl, c[2 * p],     gil * ggl);
        float ch = fmaf(gfh, c[2 * p + 1], gih * ggh);
        c[2 * p]     = cl;
        c[2 * p + 1] = ch;
        // tanh(c): pairs 0,1 MUFU; pairs 2,3 poly
        u64 tc2;
        if (p < 2) {
            tc2 = pack2(tanh_fast(cl), tanh_fast(ch));
        } else {
            tc2 = tanh_poly2(pack2(cl, ch), B);
            runmax = fmaxf(runmax, fmaxf(fabsf(cl), fabsf(ch)));
        }
        // o gate: poly
        u64 go2 = fma2(tanh_poly2(ao2, B), halfc, halfc);
        runmax = fmaxf(runmax, fmaxf(fabsf(aol), fabsf(aoh)));
        // projection accumulate (packed)
        part2 = fma2(mul2(go2, tc2), wr[p], part2);
    }
    // never-taken (by range analysis) exact fallback
    if (__any_sync(FULLM, runmax > FALLBACK)) {
        part2 = 0ull;
#pragma unroll
        for (int p = 0; p < 4; p++) {
            uint32_t off = (uint32_t)(p * 4) * 256u;
            u64 who = pack2(lds32v(whaddr + off + 512), lds32v(whaddr + off + 640));
            u64 wbo = pack2(lds32v(wbaddr + off + 512), lds32v(wbaddr + off + 640));
            u64 ao2 = fma2(x2, wx[p][2], fma2(h2, who, wbo));
            float aol, aoh;
            unpack2(ao2, aol, aoh);
            u64 go2 = pack2(fmaf(tanh_fast(aol), 0.5f, 0.5f),
                            fmaf(tanh_fast(aoh), 0.5f, 0.5f));
            u64 tc2 = pack2(tanh_fast(c[2 * p]), tanh_fast(c[2 * p + 1]));
            part2 = fma2(mul2(go2, tc2), wr[p], part2);
        }
    }
    float pl, ph;
    unpack2(part2, pl, ph);
    float ps = pl + ph;
#pragma unroll
    for (int s = 16; s; s >>= 1)
        ps += __shfl_xor_sync(FULLM, ps, s);
    return ps;
}

// ---------------------------------------------------------------------------
// Main kernel: 1 warp per batch element, 4 warps/block, 5 blocks/SM.
// ---------------------------------------------------------------------------
__global__ __launch_bounds__(128, 5) void lstm_kernel(
    const float* __restrict__ x,
    const float* __restrict__ b2,
    float* __restrict__ out)
{
    __shared__ float sbuf[4][TLEN + 8];
    // Whh / bias planes: [layer][pair][gate][lo|hi][lane]  (4 KB each)
    __shared__ float s_wh[2][4][4][2][32];
    __shared__ float s_wb[2][4][4][2][32];

    int tid = threadIdx.x;
    int warp = tid >> 5;
    int lane = tid & 31;
    int b = blockIdx.x * 4 + warp;
    const float* xb = x + (size_t)b * TLEN;

    // cooperative de-interleaved copy of Whh/bias into smem planes
    for (int i = tid; i < 1024; i += 128) {
        int ln    = i & 31;
        int g     = (i >> 5) & 3;
        int p     = (i >> 7) & 3;
        int layer = i >> 9;
        float2 vh = g_wh2[layer][p][g][ln];
        float2 vb = g_wb2[layer][p][g][ln];
        s_wh[layer][p][g][0][ln] = vh.x;
        s_wh[layer][p][g][1][ln] = vh.y;
        s_wb[layer][p][g][0][ln] = vb.x;
        s_wb[layer][p][g][1][ln] = vb.y;
    }
    __syncthreads();

    u64 B[NPOLY];
#pragma unroll
    for (int m = 0; m < NPOLY; m++) {
        float cm = g_poly[m];
        B[m] = pack2(cm, cm);
    }

    u64 wx[4][4], wr[4];
    float c[8];

    // ---------------- pass 1: layer 0 ----------------
#pragma unroll
    for (int p = 0; p < 4; p++) {
#pragma unroll
        for (int gte = 0; gte < 4; gte++)
            wx[p][gte] = ldp(&g_wx2[0][p][gte][lane]);
        wr[p] = ldp(&g_wr2[0][p][lane]);
        c[2 * p] = 0.0f; c[2 * p + 1] = 0.0f;
    }
    uint32_t whaddr = smem_u32(&s_wh[0][0][0][0][lane]);
    uint32_t wbaddr = smem_u32(&s_wb[0][0][0][0][lane]);
    float h = 0.0f;
    float xr = 0.0f;
    for (int t = 0; t < TLEN; t++) {
        if ((t & 31) == 0) {
            int ti = t + lane;
            xr = xb[(ti < TLEN) ? ti : (TLEN - 1)];
        }
        float xv = __shfl_sync(FULLM, xr, t & 31);
        h = lstm_step(xv, h, wx, wr, c, B, whaddr, wbaddr);
        if (lane == 0) sbuf[warp][t] = h;
    }
    __syncwarp();

    // ---------------- pass 2: layer 1 + fused head ----------------
#pragma unroll
    for (int p = 0; p < 4; p++) {
#pragma unroll
        for (int gte = 0; gte < 4; gte++)
            wx[p][gte] = ldp(&g_wx2[1][p][gte][lane]);
        wr[p] = ldp(&g_wr2[1][p][lane]);
        c[2 * p] = 0.0f; c[2 * p + 1] = 0.0f;
    }
    whaddr = smem_u32(&s_wh[1][0][0][0][lane]);
    wbaddr = smem_u32(&s_wb[1][0][0][0][lane]);
    h = 0.0f;
    float a0 = 0.0f, a1 = 0.0f, a2 = 0.0f, a3 = 0.0f;
    for (int t = 0; t < TLEN; t++) {
        float xv = sbuf[warp][t];
        h = lstm_step(xv, h, wx, wr, c, B, whaddr, wbaddr);
        const float* wrow = g_w1t + t * 128;
        a0 = fmaf(h, wrow[lane     ], a0);
        a1 = fmaf(h, wrow[lane + 32], a1);
        a2 = fmaf(h, wrow[lane + 64], a2);
        a3 = fmaf(h, wrow[lane + 96], a3);
    }

    // head: out = relu(acc + b1) @ W2 + b2   (padding is zero -> no effect)
    float s = fmaxf(a0 + g_b1p[lane     ], 0.0f) * g_w2p[lane     ]
            + fmaxf(a1 + g_b1p[lane + 32], 0.0f) * g_w2p[lane + 32]
            + fmaxf(a2 + g_b1p[lane + 64], 0.0f) * g_w2p[lane + 64]
            + fmaxf(a3 + g_b1p[lane + 96], 0.0f) * g_w2p[lane + 96];
#pragma unroll
    for (int sf = 16; sf; sf >>= 1)
        s += __shfl_xor_sync(FULLM, s, sf);
    if (lane == 0) out[b] = s + b2[0];
}

// ---------------------------------------------------------------------------
// kernel_launch
// ---------------------------------------------------------------------------
extern "C" void kernel_launch(void* const* d_in, const int* in_sizes, int n_in,
                              void* d_out, int out_size)
{
    const float* x    = (const float*)d_in[0];
    const float* Wih0 = (const float*)d_in[1];
    const float* Whh0 = (const float*)d_in[2];
    const float* bih0 = (const float*)d_in[3];
    const float* bhh0 = (const float*)d_in[4];
    const float* Whr0 = (const float*)d_in[5];
    const float* Wih1 = (const float*)d_in[6];
    const float* Whh1 = (const float*)d_in[7];
    const float* bih1 = (const float*)d_in[8];
    const float* bhh1 = (const float*)d_in[9];
    const float* Whr1 = (const float*)d_in[10];
    const float* W1   = (const float*)d_in[11];
    const float* b1   = (const float*)d_in[12];
    const float* W2   = (const float*)d_in[13];
    const float* b2   = (const float*)d_in[14];
    float* out = (float*)d_out;

    int B = in_sizes[0] / TLEN;   // 16384

    prep_kernel<<<TLEN + 1, 128>>>(Wih0, Whh0, bih0, bhh0, Whr0,
                                   Wih1, Whh1, bih1, bhh1, Whr1,
                                   W1, b1, W2);
    lstm_kernel<<<B / 4, 128>>>(x, b2, out);
}

// round 12
// speedup vs baseline: 1.1518x; 1.1518x over previous
#include <cuda_runtime.h>
#include <cstdint>

// ---------------------------------------------------------------------------
// voltageNN: 2-layer LSTM (H=256, proj P=1, in=1, T=1000) + MLP head, B=16384.
// MUFU-dominant split (k=8): i, f, g gates and tanh(c) (32 acts/step) on MUFU;
// ONLY the o gate (8 acts/step, off the c->proj critical path) on a deg-9 odd
// Chebyshev poly on [-1,1] via packed fma.rn.f32x2. Whh in SMEM (LDS.64; 4KB
// per step, within crossbar budget), wx/wb/wr in regs, 4 blocks/SM.
// Runtime double-precision fit; exact-MUFU fallback for |a_o| > 0.95.
// ---------------------------------------------------------------------------

#define HID   256
#define TLEN  1000
#define FULLM 0xffffffffu
#define FIT_L    1.0
#define FALLBACK 0.95f
#define NPOLY 5            // deg-9 odd: coeffs of u^1..u^9

typedef unsigned long long u64;

// Packed f32-pair weights: [layer][pair 0..3][gate i,f,o,g][lane].
// lo = unit (lane + 64*pair), hi = unit (+32). i/f/o pre-scaled by 0.5
// (sigmoid(x) = 0.5*tanh(0.5x)+0.5).
__device__ float2 g_wx2[2][4][4][32];
__device__ float2 g_wh2[2][4][4][32];
__device__ float2 g_wb2[2][4][4][32];
__device__ float2 g_wr2[2][4][32];       // projection Whr pairs
__device__ float  g_poly[NPOLY];         // tanh odd-poly coeffs (deg 9)
__device__ float  g_w1t[TLEN * 128];     // W1 transposed + padded: [t][j]
__device__ float  g_b1p[128];
__device__ float  g_w2p[128];

// ---- f32x2 packed helpers (sm_100+) ----
__device__ __forceinline__ u64 pack2(float lo, float hi) {
    u64 r; asm("mov.b64 %0, {%1, %2};" : "=l"(r) : "f"(lo), "f"(hi)); return r;
}
__device__ __forceinline__ void unpack2(u64 v, float& lo, float& hi) {
    asm("mov.b64 {%0, %1}, %2;" : "=f"(lo), "=f"(hi) : "l"(v));
}
__device__ __forceinline__ u64 fma2(u64 a, u64 b, u64 c) {
    u64 r; asm("fma.rn.f32x2 %0, %1, %2, %3;" : "=l"(r) : "l"(a), "l"(b), "l"(c));
    return r;
}
__device__ __forceinline__ u64 mul2(u64 a, u64 b) {
    u64 r; asm("mul.rn.f32x2 %0, %1, %2;" : "=l"(r) : "l"(a), "l"(b)); return r;
}
__device__ __forceinline__ u64 ldp(const float2* p) {
    float2 v = *p; return pack2(v.x, v.y);
}
__device__ __forceinline__ float tanh_fast(float x) {
    float y; asm("tanh.approx.f32 %0, %1;" : "=f"(y) : "f"(x)); return y;
}
__device__ __forceinline__ uint32_t smem_u32(const void* p) {
    uint32_t a;
    asm("{ .reg .u64 t; cvta.to.shared.u64 t, %1; cvt.u32.u64 %0, t; }"
        : "=r"(a) : "l"(p));
    return a;
}
// volatile LDS.64: keeps loop-invariant weights out of the register budget.
__device__ __forceinline__ u64 lds64v(uint32_t addr) {
    u64 r; asm volatile("ld.shared.b64 %0, [%1];" : "=l"(r) : "r"(addr));
    return r;
}
// deg-9 odd polynomial tanh on packed pair (valid on |u| <= FIT_L).
__device__ __forceinline__ u64 tanh_poly2(u64 u2, const u64* B) {
    u64 s2 = mul2(u2, u2);
    u64 p = B[4];
    p = fma2(p, s2, B[3]);
    p = fma2(p, s2, B[2]);
    p = fma2(p, s2, B[1]);
    p = fma2(p, s2, B[0]);
    return mul2(p, u2);
}

// ---------------------------------------------------------------------------
// Prep kernel: pack/transpose weights + runtime Chebyshev fit of tanh.
// grid = TLEN+1 blocks x 128 threads.
// ---------------------------------------------------------------------------
__global__ void prep_kernel(
    const float* __restrict__ Wih0, const float* __restrict__ Whh0,
    const float* __restrict__ bih0, const float* __restrict__ bhh0,
    const float* __restrict__ Whr0,
    const float* __restrict__ Wih1, const float* __restrict__ Whh1,
    const float* __restrict__ bih1, const float* __restrict__ bhh1,
    const float* __restrict__ Whr1,
    const float* __restrict__ W1,  const float* __restrict__ b1,
    const float* __restrict__ W2)
{
    int tid = threadIdx.x;
    int blk = blockIdx.x;
    if (blk < TLEN) {
        int t = blk;
        int j = tid;  // 0..127
        g_w1t[t * 128 + j] = (j < 100) ? W1[j * TLEN + t] : 0.0f;
        return;
    }
    // ---- pack LSTM weights: 2 layers x 4 pairs x 32 lanes ----
    for (int i = tid; i < 256; i += 128) {
        int layer = i >> 7;
        int rem   = i & 127;
        int p     = rem >> 5;
        int lane  = rem & 31;
        int klo = lane + 64 * p;
        int khi = klo + 32;
        const float* Wih = layer ? Wih1 : Wih0;
        const float* Whh = layer ? Whh1 : Whh0;
        const float* bih = layer ? bih1 : bih0;
        const float* bhh = layer ? bhh1 : bhh0;
        const float* Whr = layer ? Whr1 : Whr0;
        // source gate stacking: i [0,256), f [256,512), g [512,768), o [768,1024)
        const int rows[4] = {0, 256, 768, 512};   // our order: i, f, o, g
        const float scl[4] = {0.5f, 0.5f, 0.5f, 1.0f};
#pragma unroll
        for (int gte = 0; gte < 4; gte++) {
            int r = rows[gte];
            float s = scl[gte];
            g_wx2[layer][p][gte][lane] = make_float2(s * Wih[r + klo], s * Wih[r + khi]);
            g_wh2[layer][p][gte][lane] = make_float2(s * Whh[r + klo], s * Whh[r + khi]);
            g_wb2[layer][p][gte][lane] = make_float2(s * (bih[r + klo] + bhh[r + klo]),
                                                     s * (bih[r + khi] + bhh[r + khi]));
        }
        g_wr2[layer][p][lane] = make_float2(Whr[klo], Whr[khi]);
    }
    if (tid < 128) {
        g_b1p[tid] = (tid < 100) ? b1[tid] : 0.0f;
        g_w2p[tid] = (tid < 100) ? W2[tid] : 0.0f;
    }
    // ---- Chebyshev fit of tanh on [-L, L], deg 9 odd, runtime in double ----
    if (tid == 0) {
        const double PI = 3.14159265358979323846;
        const double L = FIT_L;
        const int KMAX = 9, NN = 64;
        double c[KMAX + 1];
        for (int k = 0; k <= KMAX; k++) {
            double s = 0.0;
            for (int j = 0; j < NN; j++) {
                double th = PI * (j + 0.5) / NN;
                s += tanh(L * cos(th)) * cos(k * th);
            }
            c[k] = 2.0 / NN * s;
        }
        double T[KMAX + 1][KMAX + 1];
        for (int k = 0; k <= KMAX; k++)
            for (int i = 0; i <= KMAX; i++) T[k][i] = 0.0;
        T[0][0] = 1.0; T[1][1] = 1.0;
        for (int k = 2; k <= KMAX; k++)
            for (int i = 0; i <= KMAX; i++)
                T[k][i] = 2.0 * (i > 0 ? T[k - 1][i - 1] : 0.0) - T[k - 2][i];
        double mono[KMAX + 1];
        for (int i = 0; i <= KMAX; i++) mono[i] = 0.0;
        for (int k = 1; k <= KMAX; k += 2)          // odd terms only
            for (int i = 0; i <= KMAX; i++) mono[i] += c[k] * T[k][i];
        double Lp = L;
        for (int m = 0; m < NPOLY; m++) {           // coeff of u^(2m+1)
            g_poly[m] = (float)(mono[2 * m + 1] / Lp);
            Lp *= L * L;
        }
    }
}

// ---------------------------------------------------------------------------
// One LSTM step: 8 units/lane as 4 (lo,hi) pairs.
//   MUFU: i, f, g gates + tanh(c) (32 acts).  Poly: o gate only (8 acts).
// Whh from SMEM (LDS.64). Exact-MUFU fallback for |a_o| > FALLBACK.
// ---------------------------------------------------------------------------
__device__ __forceinline__ float lstm_step(
    float xv, float h,
    const u64 (*wx)[4], const u64 (*wb)[4],
    const u64* wr, float* c, const u64* B, uint32_t whaddr)
{
    const u64 halfc = pack2(0.5f, 0.5f);
    u64 x2 = pack2(xv, xv);
    u64 h2 = pack2(h, h);
    u64 part2 = 0ull;
    float runmax = 0.0f;
#pragma unroll
    for (int p = 0; p < 4; p++) {
        // Whh from shared (loop-invariant; deliberately not in regs)
        u64 whi = lds64v(whaddr + (p * 4 + 0) * 256);
        u64 whf = lds64v(whaddr + (p * 4 + 1) * 256);
        u64 who = lds64v(whaddr + (p * 4 + 2) * 256);
        u64 whg = lds64v(whaddr + (p * 4 + 3) * 256);
        u64 ai2 = fma2(x2, wx[p][0], fma2(h2, whi, wb[p][0]));
        u64 af2 = fma2(x2, wx[p][1], fma2(h2, whf, wb[p][1]));
        u64 ao2 = fma2(x2, wx[p][2], fma2(h2, who, wb[p][2]));
        u64 ag2 = fma2(x2, wx[p][3], fma2(h2, whg, wb[p][3]));
        float ail, aih, afl, afh, agl, agh, aol, aoh;
        unpack2(ai2, ail, aih);
        unpack2(af2, afl, afh);
        unpack2(ag2, agl, agh);
        unpack2(ao2, aol, aoh);
        // MUFU: i, f (sigmoid via 0.5-prescaled tanh), g (tanh)
        float gil = fmaf(tanh_fast(ail), 0.5f, 0.5f);
        float gih = fmaf(tanh_fast(aih), 0.5f, 0.5f);
        float gfl = fmaf(tanh_fast(afl), 0.5f, 0.5f);
        float gfh = fmaf(tanh_fast(afh), 0.5f, 0.5f);
        float ggl = tanh_fast(agl);
        float ggh = tanh_fast(agh);
        // cell update (scalar)
        float cl = fmaf(gfl, c[2 * p],     gil * ggl);
        float ch = fmaf(gfh, c[2 * p + 1], gih * ggh);
        c[2 * p]     = cl;
        c[2 * p + 1] = ch;
        // tanh(c) on MUFU (latency-critical path)
        u64 tc2 = pack2(tanh_fast(cl), tanh_fast(ch));
        // o gate: deg-9 poly on the fma pipe (runs parallel to MUFU burst)
        u64 go2 = fma2(tanh_poly2(ao2, B), halfc, halfc);
        runmax = fmaxf(runmax, fmaxf(fabsf(aol), fabsf(aoh)));
        // projection accumulate (packed)
        part2 = fma2(mul2(go2, tc2), wr[p], part2);
    }
    // never-taken (by range analysis) exact fallback for the o-gate path
    if (__any_sync(FULLM, runmax > FALLBACK)) {
        part2 = 0ull;
#pragma unroll
        for (int p = 0; p < 4; p++) {
            u64 who = lds64v(whaddr + (p * 4 + 2) * 256);
            u64 ao2 = fma2(x2, wx[p][2], fma2(h2, who, wb[p][2]));
            float aol, aoh;
            unpack2(ao2, aol, aoh);
            u64 go2 = pack2(fmaf(tanh_fast(aol), 0.5f, 0.5f),
                            fmaf(tanh_fast(aoh), 0.5f, 0.5f));
            u64 tc2 = pack2(tanh_fast(c[2 * p]), tanh_fast(c[2 * p + 1]));
            part2 = fma2(mul2(go2, tc2), wr[p], part2);
        }
    }
    float pl, ph;
    unpack2(part2, pl, ph);
    float ps = pl + ph;
#pragma unroll
    for (int s = 16; s; s >>= 1)
        ps += __shfl_xor_sync(FULLM, ps, s);
    return ps;
}

// ---------------------------------------------------------------------------
// Main kernel: 1 warp per batch element, 4 warps/block, 4 blocks/SM.
// ---------------------------------------------------------------------------
__global__ __launch_bounds__(128, 4) void lstm_kernel(
    const float* __restrict__ x,
    const float* __restrict__ b2,
    float* __restrict__ out)
{
    __shared__ float sbuf[4][TLEN + 8];
    __shared__ u64 s_wh[2][4][4][32];   // both layers' Whh (8 KB)

    int tid = threadIdx.x;
    int warp = tid >> 5;
    int lane = tid & 31;
    int b = blockIdx.x * 4 + warp;
    const float* xb = x + (size_t)b * TLEN;

    // cooperative copy of Whh into smem
    {
        const u64* src = reinterpret_cast<const u64*>(&g_wh2[0][0][0][0]);
        u64* dst = &s_wh[0][0][0][0];
        for (int i = tid; i < 2 * 4 * 4 * 32; i += 128) dst[i] = src[i];
    }
    __syncthreads();

    u64 B[NPOLY];
#pragma unroll
    for (int m = 0; m < NPOLY; m++) {
        float cm = g_poly[m];
        B[m] = pack2(cm, cm);
    }

    u64 wx[4][4], wb[4][4], wr[4];
    float c[8];

    // ---------------- pass 1: layer 0 ----------------
#pragma unroll
    for (int p = 0; p < 4; p++) {
#pragma unroll
        for (int gte = 0; gte < 4; gte++) {
            wx[p][gte] = ldp(&g_wx2[0][p][gte][lane]);
            wb[p][gte] = ldp(&g_wb2[0][p][gte][lane]);
        }
        wr[p] = ldp(&g_wr2[0][p][lane]);
        c[2 * p] = 0.0f; c[2 * p + 1] = 0.0f;
    }
    uint32_t whaddr = smem_u32(&s_wh[0][0][0][lane]);
    float h = 0.0f;
    float xr = 0.0f;
    for (int t = 0; t < TLEN; t++) {
        if ((t & 31) == 0) {
            int ti = t + lane;
            xr = xb[(ti < TLEN) ? ti : (TLEN - 1)];
        }
        float xv = __shfl_sync(FULLM, xr, t & 31);
        h = lstm_step(xv, h, wx, wb, wr, c, B, whaddr);
        if (lane == 0) sbuf[warp][t] = h;
    }
    __syncwarp();

    // ---------------- pass 2: layer 1 + fused head ----------------
#pragma unroll
    for (int p = 0; p < 4; p++) {
#pragma unroll
        for (int gte = 0; gte < 4; gte++) {
            wx[p][gte] = ldp(&g_wx2[1][p][gte][lane]);
            wb[p][gte] = ldp(&g_wb2[1][p][gte][lane]);
        }
        wr[p] = ldp(&g_wr2[1][p][lane]);
        c[2 * p] = 0.0f; c[2 * p + 1] = 0.0f;
    }
    whaddr = smem_u32(&s_wh[1][0][0][lane]);
    h = 0.0f;
    float a0 = 0.0f, a1 = 0.0f, a2 = 0.0f, a3 = 0.0f;
    for (int t = 0; t < TLEN; t++) {
        float xv = sbuf[warp][t];
        h = lstm_step(xv, h, wx, wb, wr, c, B, whaddr);
        const float* wrow = g_w1t + t * 128;
        a0 = fmaf(h, wrow[lane     ], a0);
        a1 = fmaf(h, wrow[lane + 32], a1);
        a2 = fmaf(h, wrow[lane + 64], a2);
        a3 = fmaf(h, wrow[lane + 96], a3);
    }

    // head: out = relu(acc + b1) @ W2 + b2   (padding is zero -> no effect)
    float s = fmaxf(a0 + g_b1p[lane     ], 0.0f) * g_w2p[lane     ]
            + fmaxf(a1 + g_b1p[lane + 32], 0.0f) * g_w2p[lane + 32]
            + fmaxf(a2 + g_b1p[lane + 64], 0.0f) * g_w2p[lane + 64]
            + fmaxf(a3 + g_b1p[lane + 96], 0.0f) * g_w2p[lane + 96];
#pragma unroll
    for (int sf = 16; sf; sf >>= 1)
        s += __shfl_xor_sync(FULLM, s, sf);
    if (lane == 0) out[b] = s + b2[0];
}

// ---------------------------------------------------------------------------
// kernel_launch
// ---------------------------------------------------------------------------
extern "C" void kernel_launch(void* const* d_in, const int* in_sizes, int n_in,
                              void* d_out, int out_size)
{
    const float* x    = (const float*)d_in[0];
    const float* Wih0 = (const float*)d_in[1];
    const float* Whh0 = (const float*)d_in[2];
    const float* bih0 = (const float*)d_in[3];
    const float* bhh0 = (const float*)d_in[4];
    const float* Whr0 = (const float*)d_in[5];
    const float* Wih1 = (const float*)d_in[6];
    const float* Whh1 = (const float*)d_in[7];
    const float* bih1 = (const float*)d_in[8];
    const float* bhh1 = (const float*)d_in[9];
    const float* Whr1 = (const float*)d_in[10];
    const float* W1   = (const float*)d_in[11];
    const float* b1   = (const float*)d_in[12];
    const float* W2   = (const float*)d_in[13];
    const float* b2   = (const float*)d_in[14];
    float* out = (float*)d_out;

    int B = in_sizes[0] / TLEN;   // 16384

    prep_kernel<<<TLEN + 1, 128>>>(Wih0, Whh0, bih0, bhh0, Whr0,
                                   Wih1, Whh1, bih1, bhh1, Whr1,
                                   W1, b1, W2);
    lstm_kernel<<<B / 4, 128>>>(x, b2, out);
}